// round 13
// baseline (speedup 1.0000x reference)
#include <cuda_runtime.h>
#include <cuda_fp16.h>

typedef unsigned int u32;

#define TT   512
#define BB   1024
#define OBSN 64
#define HH   256
#define AA   16
#define BM   8
#define NCTA 128
#define NTH  512
#define BKP  328          // B row stride in halfs (conflict-free LDSM)
#define HPR  144          // s_hp row stride (a*9+r addressing)

__device__ __forceinline__ u32 s2u(const void* p) {
    u32 a;
    asm("{ .reg .u64 t; cvta.to.shared.u64 t, %1; cvt.u32.u64 %0, t; }" : "=r"(a) : "l"(p));
    return a;
}
// sigmoid(x) = 0.5 + 0.5*tanh(x/2)
__device__ __forceinline__ float sigt(float x) {
    float t;
    asm("tanh.approx.f32 %0, %1;" : "=f"(t) : "f"(0.5f * x));
    return fmaf(0.5f, t, 0.5f);
}
__device__ __forceinline__ uint4 ldB4(const __half* base) {
    uint4 r;
    asm volatile("ldmatrix.sync.aligned.m8n8.x4.shared.b16 {%0,%1,%2,%3}, [%4];"
                 : "=r"(r.x), "=r"(r.y), "=r"(r.z), "=r"(r.w) : "r"(s2u(base)));
    return r;
}
__device__ __forceinline__ void mma16816(float c[4], const u32* a, u32 b0, u32 b1) {
    asm volatile(
        "mma.sync.aligned.m16n8k16.row.col.f32.f16.f16.f32 "
        "{%0,%1,%2,%3}, {%4,%5,%6,%7}, {%8,%9}, {%0,%1,%2,%3};"
        : "+f"(c[0]), "+f"(c[1]), "+f"(c[2]), "+f"(c[3])
        : "r"(a[0]), "r"(a[1]), "r"(a[2]), "r"(a[3]), "r"(b0), "r"(b1));
}

__global__ void __launch_bounds__(NTH, 1) rnn_kernel(
    const float* __restrict__ obs,
    const float* __restrict__ W_in,
    const float* __restrict__ W_h,
    const float* __restrict__ b_h,
    const float* __restrict__ W_out,
    const float* __restrict__ b_out,
    float* __restrict__ out)
{
    __shared__ __align__(32) __half s_B[2][8 * BKP];   // (obs_t | h_{t-1}), double-buffered
    __shared__ float4 s_mp[2][8][32];                  // cross-K-half fragment exchange
    __shared__ float  s_hp[2][8][HPR];                 // head partials, double-buffered

    const int tid = threadIdx.x;
    const int w = tid >> 5, l = tid & 31;
    const int kh = w >> 3, m = w & 7;                  // K-half, M-group (M=32 rows)
    const int grp = l >> 2, tig = l & 3;
    const int b0 = blockIdx.x * BM;
    const int jA = 32 * m + grp;                       // tile0 rows jA, jA+8
    const int jB = jA + 16;                            // tile1 rows jB, jB+8
    const int r0 = 2 * tig, r1 = r0 + 1;
    const int jO0 = kh ? jB : jA, jO1 = jO0 + 8;       // tile this warp finalizes

    // ---- prologue: main A fragments for this warp's K-half ----
    u32 afrag[10][8];
    #pragma unroll
    for (int kt = 0; kt < 10; ++kt) {
        const int ktg = 10 * kh + kt;
        #pragma unroll
        for (int tile = 0; tile < 2; ++tile) {
            const int ja = jA + 16 * tile, jb = ja + 8;
            #pragma unroll
            for (int hk = 0; hk < 2; ++hk) {
                const int kk = ktg * 16 + 2 * tig + 8 * hk;
                float xa, ya, xb, yb;
                if (kk < OBSN) {
                    xa = W_in[ja * OBSN + kk]; ya = W_in[ja * OBSN + kk + 1];
                    xb = W_in[jb * OBSN + kk]; yb = W_in[jb * OBSN + kk + 1];
                } else {
                    xa = W_h[ja * HH + kk - OBSN]; ya = W_h[ja * HH + kk - OBSN + 1];
                    xb = W_h[jb * HH + kk - OBSN]; yb = W_h[jb * HH + kk - OBSN + 1];
                }
                __half2 ha = __floats2half2_rn(xa, ya), hb = __floats2half2_rn(xb, yb);
                afrag[kt][tile * 4 + 2 * hk]     = *(u32*)&ha;
                afrag[kt][tile * 4 + 2 * hk + 1] = *(u32*)&hb;
            }
        }
    }
    // head A-frags: warps 0-7, two k-tiles each (h cols 32w..32w+31)
    u32 a3[2][4];
    if (kh == 0) {
        #pragma unroll
        for (int tt = 0; tt < 2; ++tt) {
            const int ck = 32 * w + 16 * tt + 2 * tig;
            __half2 h0 = __floats2half2_rn(W_out[grp * HH + ck],           W_out[grp * HH + ck + 1]);
            __half2 h1 = __floats2half2_rn(W_out[(grp + 8) * HH + ck],     W_out[(grp + 8) * HH + ck + 1]);
            __half2 h2 = __floats2half2_rn(W_out[grp * HH + ck + 8],       W_out[grp * HH + ck + 9]);
            __half2 h3 = __floats2half2_rn(W_out[(grp + 8) * HH + ck + 8], W_out[(grp + 8) * HH + ck + 9]);
            a3[tt][0] = *(u32*)&h0; a3[tt][1] = *(u32*)&h1;
            a3[tt][2] = *(u32*)&h2; a3[tt][3] = *(u32*)&h3;
        }
    }
    const float bO0 = b_h[jO0], bO1 = b_h[jO1];        // bias for owned tile

    // role maps
    const bool comb = (w >= 12);                       // combiner: 128 threads, 1 (a,r) each
    const int cq = tid - 384, ca = cq & 15, cr = cq >> 4;
    const int coff = ca * 9 + cr;
    const float bo = comb ? b_out[ca] : 0.0f;
    float o_reg = 0.0f;
    const bool obw = (w >= 8 && w < 12);               // obs staging: 128 threads, 2 items
    const int oi = (w - 8) * 32 + l, orow = oi >> 5, ocp = oi & 31;

    float hs[4] = {0.f, 0.f, 0.f, 0.f};

    for (int i = tid; i < 2 * 8 * BKP / 2; i += NTH) ((u32*)s_B)[i] = 0u;
    __syncthreads();
    if (obw) {                                         // stage obs_0
        float2 v0 = *(const float2*)(obs + ((long)(b0 + orow) * TT + 0) * OBSN + 2 * ocp);
        float2 v1 = *(const float2*)(obs + ((long)(b0 + orow + 4) * TT + 0) * OBSN + 2 * ocp);
        *(__half2*)(&s_B[0][orow * BKP + 2 * ocp])       = __floats2half2_rn(v0.x, v0.y);
        *(__half2*)(&s_B[0][(orow + 4) * BKP + 2 * ocp]) = __floats2half2_rn(v1.x, v1.y);
    }
    __syncthreads();

    const long OUT_H = (long)BB * TT * AA;
    const long OUT_O = OUT_H + (long)BB * HH;

    #pragma unroll 2
    for (int t = 0; t <= TT + 1; ++t) {
        const __half* Bc = s_B[t & 1];
        float2 op0, op1;
        if (obw && t < TT) {                           // prefetch obs_{t+1}
            const int tn = (t + 1 < TT) ? t + 1 : TT - 1;
            op0 = *(const float2*)(obs + ((long)(b0 + orow) * TT + tn) * OBSN + 2 * ocp);
            op1 = *(const float2*)(obs + ((long)(b0 + orow + 4) * TT + tn) * OBSN + 2 * ocp);
        }

        // ---- combiner: finish head of step t-1 -> emit o_{t-2} (overlapped) ----
        if (comb && t >= 2) {
            const float* hp = &s_hp[(t - 1) & 1][0][0];
            float s = bo;
            #pragma unroll
            for (int w2 = 0; w2 < 8; ++w2) s += hp[w2 * HPR + coff];
            o_reg = 0.9f * o_reg + 0.1f * sigt(s);
            out[((long)(b0 + cr) * TT + (t - 2)) * AA + ca] = o_reg;
        }

        // ---- main MMA over own K-half ----
        float fown[4];
        if (t < TT) {
            float c0[4], c1[4], c2[4], c3[4];
            if (kh == 0) {
                c0[0] = bO0; c0[1] = bO0; c0[2] = bO1; c0[3] = bO1;
                #pragma unroll
                for (int i = 0; i < 4; ++i) c2[i] = 0.f;
            } else {
                c2[0] = bO0; c2[1] = bO0; c2[2] = bO1; c2[3] = bO1;
                #pragma unroll
                for (int i = 0; i < 4; ++i) c0[i] = 0.f;
            }
            #pragma unroll
            for (int i = 0; i < 4; ++i) { c1[i] = 0.f; c3[i] = 0.f; }

            const __half* Bb = Bc + (l & 7) * BKP + kh * 160 + 8 * (l >> 3);
            uint4 ba = ldB4(Bb), bn;
            #pragma unroll
            for (int p = 0; p < 5; ++p) {
                if (p < 4) bn = ldB4(Bb + (p + 1) * 32);
                mma16816(c0, &afrag[2 * p][0],     ba.x, ba.y);
                mma16816(c2, &afrag[2 * p][4],     ba.x, ba.y);
                mma16816(c1, &afrag[2 * p + 1][0], ba.z, ba.w);
                mma16816(c3, &afrag[2 * p + 1][4], ba.z, ba.w);
                ba = bn;
            }
            if (kh == 0) {                             // publish OTHER tile's fragment
                s_mp[1][m][l] = make_float4(c2[0] + c3[0], c2[1] + c3[1],
                                            c2[2] + c3[2], c2[3] + c3[3]);
                #pragma unroll
                for (int i = 0; i < 4; ++i) fown[i] = c0[i] + c1[i];
            } else {
                s_mp[0][m][l] = make_float4(c0[0] + c1[0], c0[1] + c1[1],
                                            c0[2] + c1[2], c0[3] + c1[3]);
                #pragma unroll
                for (int i = 0; i < 4; ++i) fown[i] = c2[i] + c3[i];
            }
        }

        // ---- head: warps 0-7, 2 k-tiles each ----
        if (kh == 0 && t >= 1 && t <= TT) {
            uint4 hb = ldB4(Bc + (l & 7) * BKP + OBSN + 32 * w + 8 * (l >> 3));
            float cp[4] = {0.f, 0.f, 0.f, 0.f};
            mma16816(cp, a3[0], hb.x, hb.y);
            mma16816(cp, a3[1], hb.z, hb.w);
            float* hp = s_hp[t & 1][w];
            hp[grp * 9 + r0]       = cp[0];
            hp[grp * 9 + r1]       = cp[1];
            hp[(grp + 8) * 9 + r0] = cp[2];
            hp[(grp + 8) * 9 + r1] = cp[3];
        }
        __syncthreads();                               // bar1: fragment/partial handoff

        // ---- balanced finalize: every warp updates its own 16 rows ----
        if (t < TT) {
            __half* Bn = (__half*)s_B[(t & 1) ^ 1];
            const float4 v = s_mp[kh][m][l];
            hs[0] = 0.9f * hs[0] + 0.1f * sigt(fown[0] + v.x);
            hs[1] = 0.9f * hs[1] + 0.1f * sigt(fown[1] + v.y);
            hs[2] = 0.9f * hs[2] + 0.1f * sigt(fown[2] + v.z);
            hs[3] = 0.9f * hs[3] + 0.1f * sigt(fown[3] + v.w);
            Bn[r0 * BKP + OBSN + jO0] = __float2half_rn(hs[0]);
            Bn[r1 * BKP + OBSN + jO0] = __float2half_rn(hs[1]);
            Bn[r0 * BKP + OBSN + jO1] = __float2half_rn(hs[2]);
            Bn[r1 * BKP + OBSN + jO1] = __float2half_rn(hs[3]);
            if (obw) {
                *(__half2*)(&Bn[orow * BKP + 2 * ocp])       = __floats2half2_rn(op0.x, op0.y);
                *(__half2*)(&Bn[(orow + 4) * BKP + 2 * ocp]) = __floats2half2_rn(op1.x, op1.y);
            }
        }
        __syncthreads();                               // bar2: B_next/s_mp reuse
    }

    // ---- final states: [out | h | o] ----
    out[OUT_H + (long)(b0 + r0) * HH + jO0] = hs[0];
    out[OUT_H + (long)(b0 + r1) * HH + jO0] = hs[1];
    out[OUT_H + (long)(b0 + r0) * HH + jO1] = hs[2];
    out[OUT_H + (long)(b0 + r1) * HH + jO1] = hs[3];
    if (comb)
        out[OUT_O + (long)(b0 + cr) * AA + ca] = o_reg;
}

extern "C" void kernel_launch(void* const* d_in, const int* in_sizes, int n_in,
                              void* d_out, int out_size) {
    const float* obs   = (const float*)d_in[0];
    const float* W_in  = (const float*)d_in[1];
    const float* W_h   = (const float*)d_in[2];
    const float* b_h   = (const float*)d_in[3];
    const float* W_out = (const float*)d_in[4];
    const float* b_out = (const float*)d_in[5];
    float* out = (float*)d_out;

    rnn_kernel<<<NCTA, NTH>>>(obs, W_in, W_h, b_h, W_out, b_out, out);
}